// round 9
// baseline (speedup 1.0000x reference)
#include <cuda_runtime.h>
#include <cstddef>

// Problem constants (from reference: N=50000, F=128, H=8, HID=8, CLS=40, E=1.6M)
#define NMAX 50000
#define HEADS 8
#define HIDC  8
#define NCLS  40
#define D1    (HEADS*HIDC)   // 64
#define D5    (HEADS*NCLS)   // 320

// Scratch (device globals; no allocation in kernel_launch)
__device__ float g_bufA[NMAX*D1];   // transformed features h of current layer
__device__ float g_bufB[NMAX*D1];   // aggregated (unnormalized) output of current layer
__device__ float g_ss[NMAX*HEADS];  // per-node src attention scalar
__device__ float g_sd[NMAX*HEADS];  // per-node dst attention scalar
__device__ float g_dn[NMAX*HEADS];  // softmax denominator (unnormalized sum of weights)
__device__ float g_h5[NMAX*D5];     // layer-5 transformed features
__device__ float g_agg5[NMAX*D5];   // layer-5 aggregation

__device__ __forceinline__ float lrelu(float x) { return x > 0.f ? x : 0.2f * x; }

__device__ __forceinline__ void red4(float* p, float a, float b, float c, float d) {
    asm volatile("red.global.add.v4.f32 [%0], {%1,%2,%3,%4};"
                 :: "l"(p), "f"(a), "f"(b), "f"(c), "f"(d) : "memory");
}
__device__ __forceinline__ void red1(float* p, float v) {
    asm volatile("red.global.add.f32 [%0], %1;" :: "l"(p), "f"(v) : "memory");
}

// ---------------------------------------------------------------------------
// GEMM for layers 1-4: h = act(x) @ W ; also computes per-node attention
// scalars ss = sum_c h[h,c]*a_src[h,c], sd likewise.
// ACT: input is previous layer's unnormalized aggregation -> apply
//      lrelu(agg/denom + bias) on the fly.
// ---------------------------------------------------------------------------
template<int K, bool ACT>
__global__ __launch_bounds__(256)
void gemm_node(const float* __restrict__ x, const float* __restrict__ W,
               const float* __restrict__ asrc, const float* __restrict__ adst,
               const float* __restrict__ bprev,
               float* __restrict__ hout, int n)
{
    __shared__ float Ws[K*D1];
    __shared__ float As[D1], Ad[D1], Bp[D1];
    for (int i = threadIdx.x; i < K*D1; i += 256) Ws[i] = W[i];
    if (threadIdx.x < D1) {
        As[threadIdx.x] = asrc[threadIdx.x];
        Ad[threadIdx.x] = adst[threadIdx.x];
        Bp[threadIdx.x] = ACT ? bprev[threadIdx.x] : 0.f;
    }
    __syncthreads();

    int node = blockIdx.x * 256 + threadIdx.x;
    if (node >= n) return;

    float acc[D1];
#pragma unroll
    for (int c = 0; c < D1; c++) acc[c] = 0.f;

    float rdn[HEADS];
    if (ACT) {
#pragma unroll
        for (int hh = 0; hh < HEADS; hh++) rdn[hh] = 1.f / g_dn[node*HEADS + hh];
    }

    const float4* xr = (const float4*)(x + (size_t)node * K);
#pragma unroll
    for (int k4 = 0; k4 < K/4; k4++) {
        float4 xv = xr[k4];
        float xs[4] = {xv.x, xv.y, xv.z, xv.w};
#pragma unroll
        for (int j = 0; j < 4; j++) {
            int k = k4*4 + j;
            float v = xs[j];
            if (ACT) v = lrelu(v * rdn[k >> 3] + Bp[k]);
            const float* wr = &Ws[k*D1];
#pragma unroll
            for (int c = 0; c < D1; c++) acc[c] = fmaf(v, wr[c], acc[c]);
        }
    }

    float* hp = hout + (size_t)node * D1;
#pragma unroll
    for (int i = 0; i < D1/4; i++)
        ((float4*)hp)[i] = make_float4(acc[4*i], acc[4*i+1], acc[4*i+2], acc[4*i+3]);

#pragma unroll
    for (int hh = 0; hh < HEADS; hh++) {
        float a = 0.f, b = 0.f;
#pragma unroll
        for (int c = 0; c < HIDC; c++) {
            a = fmaf(acc[hh*HIDC + c], As[hh*HIDC + c], a);
            b = fmaf(acc[hh*HIDC + c], Ad[hh*HIDC + c], b);
        }
        g_ss[node*HEADS + hh] = a;
        g_sd[node*HEADS + hh] = b;
    }
}

// ---------------------------------------------------------------------------
// GEMM for layer 5: per-head column slice (40 cols), grid.y = head
// ---------------------------------------------------------------------------
__global__ __launch_bounds__(128)
void gemm5_node(const float* __restrict__ xagg, const float* __restrict__ bprev,
                const float* __restrict__ W5,
                const float* __restrict__ as5, const float* __restrict__ ad5, int n)
{
    int head = blockIdx.y;
    __shared__ float Ws[D1*NCLS];
    __shared__ float As[NCLS], Ad[NCLS], Bp[D1];
    for (int i = threadIdx.x; i < D1*NCLS; i += 128) {
        int k = i / NCLS, c = i % NCLS;
        Ws[i] = W5[k*D5 + head*NCLS + c];
    }
    if (threadIdx.x < NCLS) {
        As[threadIdx.x] = as5[head*NCLS + threadIdx.x];
        Ad[threadIdx.x] = ad5[head*NCLS + threadIdx.x];
    }
    if (threadIdx.x < D1) Bp[threadIdx.x] = bprev[threadIdx.x];
    __syncthreads();

    int node = blockIdx.x * 128 + threadIdx.x;
    if (node >= n) return;

    float rdn[HEADS];
#pragma unroll
    for (int hh = 0; hh < HEADS; hh++) rdn[hh] = 1.f / g_dn[node*HEADS + hh];

    float acc[NCLS];
#pragma unroll
    for (int c = 0; c < NCLS; c++) acc[c] = 0.f;

    const float4* xr = (const float4*)(xagg + (size_t)node * D1);
#pragma unroll
    for (int k4 = 0; k4 < D1/4; k4++) {
        float4 xv = xr[k4];
        float xs[4] = {xv.x, xv.y, xv.z, xv.w};
#pragma unroll
        for (int j = 0; j < 4; j++) {
            int k = k4*4 + j;
            float v = lrelu(xs[j] * rdn[k >> 3] + Bp[k]);
            const float* wr = &Ws[k*NCLS];
#pragma unroll
            for (int c = 0; c < NCLS; c++) acc[c] = fmaf(v, wr[c], acc[c]);
        }
    }

    float* hp = g_h5 + (size_t)node * D5 + head*NCLS;
#pragma unroll
    for (int i = 0; i < NCLS/4; i++)
        ((float4*)hp)[i] = make_float4(acc[4*i], acc[4*i+1], acc[4*i+2], acc[4*i+3]);

    float a = 0.f, b = 0.f;
#pragma unroll
    for (int c = 0; c < NCLS; c++) {
        a = fmaf(acc[c], As[c], a);
        b = fmaf(acc[c], Ad[c], b);
    }
    g_ss[node*HEADS + head] = a;
    g_sd[node*HEADS + head] = b;
}

// ---------------------------------------------------------------------------
// Node init: self-loop term. denom = w_self; agg = h * w_self.
// One thread per (node, head).
// ---------------------------------------------------------------------------
__global__ void node_init(const float* __restrict__ h, float* __restrict__ agg, int n)
{
    int idx = blockIdx.x * 256 + threadIdx.x;
    if (idx >= n*HEADS) return;
    float w = __expf(lrelu(g_ss[idx] + g_sd[idx]));
    g_dn[idx] = w;
    int node = idx >> 3, head = idx & 7;
    const float4* hp = (const float4*)(h + (size_t)node*D1 + head*HIDC);
    float4* ap = (float4*)(agg + (size_t)node*D1 + head*HIDC);
#pragma unroll
    for (int i = 0; i < 2; i++) {
        float4 v = hp[i];
        ap[i] = make_float4(v.x*w, v.y*w, v.z*w, v.w*w);
    }
}

__global__ void node_init5(int n)
{
    int idx = blockIdx.x * 256 + threadIdx.x;
    if (idx >= n*HEADS) return;
    float w = __expf(lrelu(g_ss[idx] + g_sd[idx]));
    g_dn[idx] = w;
    int node = idx >> 3, head = idx & 7;
    const float4* hp = (const float4*)(g_h5 + (size_t)node*D5 + head*NCLS);
    float4* ap = (float4*)(g_agg5 + (size_t)node*D5 + head*NCLS);
#pragma unroll
    for (int i = 0; i < NCLS/4; i++) {
        float4 v = hp[i];
        ap[i] = make_float4(v.x*w, v.y*w, v.z*w, v.w*w);
    }
}

// ---------------------------------------------------------------------------
// Single fused edge pass: w = exp(lrelu(ss[src]+sd[dst]));
//   agg[dst] += w*h[src] (red.v4),  denom[dst] += w
// 16 threads per edge: thread t -> head=t>>1, quad=t&1 (4 channels)
// ---------------------------------------------------------------------------
__global__ __launch_bounds__(256)
void edge_agg(const int* __restrict__ src, const int* __restrict__ dst,
              const float* __restrict__ h, float* __restrict__ agg, int E)
{
    int gid = blockIdx.x * 256 + threadIdx.x;
    int e = gid >> 4;
    if (e >= E) return;
    int t = gid & 15;
    int s = __ldg(src + e), d = __ldg(dst + e);
    int head = t >> 1, quad = t & 1;
    float w = __expf(lrelu(g_ss[s*HEADS + head] + g_sd[d*HEADS + head]));
    const float4 hv = *(const float4*)(h + (size_t)s*D1 + head*HIDC + quad*4);
    red4(agg + (size_t)d*D1 + head*HIDC + quad*4, hv.x*w, hv.y*w, hv.z*w, hv.w*w);
    if (!quad) red1(&g_dn[d*HEADS + head], w);
}

// Layer-5 edge pass: 16 threads/edge, each handles 5 float4 (20 floats)
__global__ __launch_bounds__(256)
void edge_agg5(const int* __restrict__ src, const int* __restrict__ dst, int E)
{
    int gid = blockIdx.x * 256 + threadIdx.x;
    int e = gid >> 4;
    if (e >= E) return;
    int t = gid & 15;
    int s = __ldg(src + e), d = __ldg(dst + e);
    int head = t >> 1, half = t & 1;
    float w = __expf(lrelu(g_ss[s*HEADS + head] + g_sd[d*HEADS + head]));
    const float4* hp = (const float4*)(g_h5 + (size_t)s*D5 + head*NCLS + half*20);
    float* ap = g_agg5 + (size_t)d*D5 + head*NCLS + half*20;
#pragma unroll
    for (int j = 0; j < 5; j++) {
        float4 hv = hp[j];
        red4(ap + j*4, hv.x*w, hv.y*w, hv.z*w, hv.w*w);
    }
    if (!half) red1(&g_dn[d*HEADS + head], w);
}

// ---------------------------------------------------------------------------
// Finalize: mean over heads of normalized agg5, + b5, log_softmax -> out
// ---------------------------------------------------------------------------
__global__ __launch_bounds__(128)
void finalize(const float* __restrict__ b5, float* __restrict__ out, int n)
{
    int node = blockIdx.x * 128 + threadIdx.x;
    if (node >= n) return;
    float rdn[HEADS];
#pragma unroll
    for (int hh = 0; hh < HEADS; hh++) rdn[hh] = 1.f / g_dn[node*HEADS + hh];
    float v[NCLS];
#pragma unroll
    for (int c = 0; c < NCLS; c++) v[c] = 0.f;
#pragma unroll
    for (int hh = 0; hh < HEADS; hh++) {
        const float* ap = g_agg5 + (size_t)node*D5 + hh*NCLS;
#pragma unroll
        for (int c = 0; c < NCLS; c++) v[c] = fmaf(ap[c], rdn[hh], v[c]);
    }
    float m = -1e30f;
#pragma unroll
    for (int c = 0; c < NCLS; c++) {
        v[c] = v[c] * 0.125f + b5[c];
        m = fmaxf(m, v[c]);
    }
    float sum = 0.f;
#pragma unroll
    for (int c = 0; c < NCLS; c++) sum += expf(v[c] - m);
    float lse = m + logf(sum);
    float* op = out + (size_t)node*NCLS;
#pragma unroll
    for (int c = 0; c < NCLS; c++) op[c] = v[c] - lse;
}

// ---------------------------------------------------------------------------
extern "C" void kernel_launch(void* const* d_in, const int* in_sizes, int n_in,
                              void* d_out, int out_size)
{
    const float* x = (const float*)d_in[0];
    const int*   ei = (const int*)d_in[1];
    int E = in_sizes[1] / 2;
    int n = in_sizes[0] / 128;
    const int* srcp = ei;
    const int* dstp = ei + E;

    const float *W[5], *as_[5], *ad_[5], *bs[5];
    for (int l = 0; l < 5; l++) {
        W[l]   = (const float*)d_in[2 + 4*l];
        as_[l] = (const float*)d_in[3 + 4*l];
        ad_[l] = (const float*)d_in[4 + 4*l];
        bs[l]  = (const float*)d_in[5 + 4*l];
    }

    float *bufA, *bufB;
    cudaGetSymbolAddress((void**)&bufA, g_bufA);
    cudaGetSymbolAddress((void**)&bufB, g_bufB);

    int gn256   = (n + 255) / 256;
    int gn128   = (n + 127) / 128;
    int gnh256  = (n*HEADS + 255) / 256;
    int ge      = (E*16 + 255) / 256;

    // Layer 1: input = raw x [N,128]
    gemm_node<128, false><<<gn256, 256>>>(x, W[0], as_[0], ad_[0], nullptr, bufA, n);
    node_init<<<gnh256, 256>>>(bufA, bufB, n);
    edge_agg<<<ge, 256>>>(srcp, dstp, bufA, bufB, E);

    // Layers 2-4: input = lrelu(bufB/denom + b_prev)
    for (int l = 1; l <= 3; l++) {
        gemm_node<64, true><<<gn256, 256>>>(bufB, W[l], as_[l], ad_[l], bs[l-1], bufA, n);
        node_init<<<gnh256, 256>>>(bufA, bufB, n);
        edge_agg<<<ge, 256>>>(srcp, dstp, bufA, bufB, E);
    }

    // Layer 5
    gemm5_node<<<dim3(gn128, HEADS), 128>>>(bufB, bs[3], W[4], as_[4], ad_[4], n);
    node_init5<<<gnh256, 256>>>(n);
    edge_agg5<<<ge, 256>>>(srcp, dstp, E);

    finalize<<<gn128, 128>>>(bs[4], (float*)d_out, n);
}

// round 15
// speedup vs baseline: 1.8345x; 1.8345x over previous
#include <cuda_runtime.h>
#include <cstddef>

// Problem constants
#define NMAX 50000
#define EMAX 1600000
#define HEADS 8
#define HIDC  8
#define NCLS  40
#define D1    (HEADS*HIDC)   // 64
#define D5    (HEADS*NCLS)   // 320

// Scratch
__device__ float g_bufA[NMAX*D1];
__device__ float g_bufB[NMAX*D1];
__device__ float g_ss[NMAX*HEADS];
__device__ float g_sd[NMAX*HEADS];
__device__ float g_dn[NMAX*HEADS];
__device__ float g_acc5[(size_t)NMAX*512];  // layer-5 aggregated x5 per head
__device__ float g_h5[NMAX*D5];             // per-head layer-5 outputs
__device__ int   g_cnt[NMAX];
__device__ int   g_row[NMAX+1];
__device__ int   g_cur[NMAX];
__device__ int   g_col[EMAX];
__device__ float g_w5a_s[HEADS*D1];
__device__ float g_w5a_d[HEADS*D1];

__device__ __forceinline__ float lrelu(float x) { return x > 0.f ? x : 0.2f * x; }

// ======================= CSR build =======================
__global__ void zero_cnt(int n) {
    int i = blockIdx.x*256 + threadIdx.x;
    if (i < n) g_cnt[i] = 0;
}
__global__ void count_kernel(const int* __restrict__ dst, int E) {
    int e = blockIdx.x*256 + threadIdx.x;
    if (e < E) atomicAdd(&g_cnt[dst[e]], 1);
}
__global__ void scan_kernel(int n) {
    __shared__ int sm[1024];
    int tid = threadIdx.x;
    int per = (n + 1023) >> 10;
    int base = tid * per;
    int s = 0;
    for (int i = 0; i < per; i++) { int idx = base+i; if (idx < n) s += g_cnt[idx]; }
    sm[tid] = s; __syncthreads();
    for (int off = 1; off < 1024; off <<= 1) {
        int v = (tid >= off) ? sm[tid-off] : 0;
        __syncthreads();
        sm[tid] += v;
        __syncthreads();
    }
    int excl = sm[tid] - s;
    for (int i = 0; i < per; i++) {
        int idx = base+i;
        if (idx < n) { g_row[idx] = excl; g_cur[idx] = excl; excl += g_cnt[idx]; }
    }
    if (tid == 1023) g_row[n] = sm[1023];
}
__global__ void scatter_kernel(const int* __restrict__ src, const int* __restrict__ dst, int E) {
    int e = blockIdx.x*256 + threadIdx.x;
    if (e < E) {
        int p = atomicAdd(&g_cur[dst[e]], 1);
        g_col[p] = src[e];
    }
}

// ======================= layers 1-4 GEMM =======================
template<int K, bool ACT>
__global__ __launch_bounds__(256)
void gemm_node(const float* __restrict__ x, const float* __restrict__ W,
               const float* __restrict__ asrc, const float* __restrict__ adst,
               const float* __restrict__ bprev,
               float* __restrict__ hout, int n)
{
    __shared__ float Ws[K*D1];
    __shared__ float As[D1], Ad[D1], Bp[D1];
    for (int i = threadIdx.x; i < K*D1; i += 256) Ws[i] = W[i];
    if (threadIdx.x < D1) {
        As[threadIdx.x] = asrc[threadIdx.x];
        Ad[threadIdx.x] = adst[threadIdx.x];
        Bp[threadIdx.x] = ACT ? bprev[threadIdx.x] : 0.f;
    }
    __syncthreads();

    int node = blockIdx.x * 256 + threadIdx.x;
    if (node >= n) return;

    float acc[D1];
#pragma unroll
    for (int c = 0; c < D1; c++) acc[c] = 0.f;

    float rdn[HEADS];
    if (ACT) {
#pragma unroll
        for (int hh = 0; hh < HEADS; hh++) rdn[hh] = 1.f / g_dn[node*HEADS + hh];
    }

    const float4* xr = (const float4*)(x + (size_t)node * K);
#pragma unroll
    for (int k4 = 0; k4 < K/4; k4++) {
        float4 xv = xr[k4];
        float xs[4] = {xv.x, xv.y, xv.z, xv.w};
#pragma unroll
        for (int j = 0; j < 4; j++) {
            int k = k4*4 + j;
            float v = xs[j];
            if (ACT) v = lrelu(v * rdn[k >> 3] + Bp[k]);
            const float* wr = &Ws[k*D1];
#pragma unroll
            for (int c = 0; c < D1; c++) acc[c] = fmaf(v, wr[c], acc[c]);
        }
    }

    float* hp = hout + (size_t)node * D1;
#pragma unroll
    for (int i = 0; i < D1/4; i++)
        ((float4*)hp)[i] = make_float4(acc[4*i], acc[4*i+1], acc[4*i+2], acc[4*i+3]);

#pragma unroll
    for (int hh = 0; hh < HEADS; hh++) {
        float a = 0.f, b = 0.f;
#pragma unroll
        for (int c = 0; c < HIDC; c++) {
            a = fmaf(acc[hh*HIDC + c], As[hh*HIDC + c], a);
            b = fmaf(acc[hh*HIDC + c], Ad[hh*HIDC + c], b);
        }
        g_ss[node*HEADS + hh] = a;
        g_sd[node*HEADS + hh] = b;
    }
}

// ======================= CSR aggregation, layers 1-4 =======================
// One warp per dst node. lane L: channels 2L,2L+1; head = L>>2.
// agg[dst] = w_self*h[dst] + sum_e w_e*h[src_e];  dn[dst] = w_self + sum w_e
__global__ __launch_bounds__(256)
void csr_agg(const float* __restrict__ h, float* __restrict__ agg, int n)
{
    int warpid = (blockIdx.x*256 + threadIdx.x) >> 5;
    if (warpid >= n) return;
    int lane = threadIdx.x & 31;
    int dst = warpid;
    int hh = lane >> 2;
    int c0 = lane * 2;

    float sd_d = g_sd[dst*HEADS + hh];
    float wself = __expf(lrelu(g_ss[dst*HEADS + hh] + sd_d));
    float2 hv = *(const float2*)(h + (size_t)dst*D1 + c0);
    float ax = hv.x * wself, ay = hv.y * wself;
    float dsum = wself;

    int beg = g_row[dst], end = g_row[dst+1];
    for (int j0 = beg; j0 < end; j0 += 32) {
        int myj = j0 + lane;
        int mysrc = (myj < end) ? g_col[myj] : 0;
        int m = min(32, end - j0);
        for (int t = 0; t < m; t++) {
            int s = __shfl_sync(0xffffffffu, mysrc, t);
            float w = __expf(lrelu(g_ss[s*HEADS + hh] + sd_d));
            float2 xv = *(const float2*)(h + (size_t)s*D1 + c0);
            ax = fmaf(w, xv.x, ax);
            ay = fmaf(w, xv.y, ay);
            if ((lane & 3) == 0) dsum += w;
        }
    }
    *(float2*)(agg + (size_t)dst*D1 + c0) = make_float2(ax, ay);
    if ((lane & 3) == 0) g_dn[dst*HEADS + hh] = dsum;
}

// ======================= layer-5 pieces =======================
// W5a[h][k] = sum_c W5[k, h*40+c] * a5[h][c]  (projected attention vectors)
__global__ void w5a_kernel(const float* __restrict__ W5,
                           const float* __restrict__ as5, const float* __restrict__ ad5)
{
    int t = blockIdx.x*128 + threadIdx.x;
    if (t >= HEADS*D1) return;
    int h = t >> 6, k = t & 63;
    float a = 0.f, b = 0.f;
    for (int c = 0; c < NCLS; c++) {
        float w = W5[k*D5 + h*NCLS + c];
        a = fmaf(w, as5[h*NCLS + c], a);
        b = fmaf(w, ad5[h*NCLS + c], b);
    }
    g_w5a_s[h*D1 + k] = a;
    g_w5a_d[h*D1 + k] = b;
}

// x5 = lrelu(aggin/dn + b4); ss/sd = x5 . W5a
__global__ __launch_bounds__(256)
void x5_kernel(const float* __restrict__ aggin, const float* __restrict__ b4,
               float* __restrict__ x5, int n)
{
    __shared__ float Ws[HEADS*D1], Wd[HEADS*D1], Bp[D1];
    for (int i = threadIdx.x; i < HEADS*D1; i += 256) { Ws[i] = g_w5a_s[i]; Wd[i] = g_w5a_d[i]; }
    if (threadIdx.x < D1) Bp[threadIdx.x] = b4[threadIdx.x];
    __syncthreads();

    int node = blockIdx.x*256 + threadIdx.x;
    if (node >= n) return;

    float rdn[HEADS];
#pragma unroll
    for (int h = 0; h < HEADS; h++) rdn[h] = 1.f / g_dn[node*HEADS + h];

    float xv[D1];
    const float4* ip = (const float4*)(aggin + (size_t)node*D1);
#pragma unroll
    for (int i = 0; i < D1/4; i++) {
        float4 v = ip[i];
        int k = i*4;
        xv[k+0] = lrelu(v.x * rdn[(k+0)>>3] + Bp[k+0]);
        xv[k+1] = lrelu(v.y * rdn[(k+1)>>3] + Bp[k+1]);
        xv[k+2] = lrelu(v.z * rdn[(k+2)>>3] + Bp[k+2]);
        xv[k+3] = lrelu(v.w * rdn[(k+3)>>3] + Bp[k+3]);
    }
    float* op = x5 + (size_t)node*D1;
#pragma unroll
    for (int i = 0; i < D1/4; i++)
        ((float4*)op)[i] = make_float4(xv[4*i], xv[4*i+1], xv[4*i+2], xv[4*i+3]);

#pragma unroll
    for (int h = 0; h < HEADS; h++) {
        float a = 0.f, b = 0.f;
#pragma unroll
        for (int k = 0; k < D1; k++) {
            a = fmaf(xv[k], Ws[h*D1 + k], a);
            b = fmaf(xv[k], Wd[h*D1 + k], b);
        }
        g_ss[node*HEADS + h] = a;
        g_sd[node*HEADS + h] = b;
    }
}

// Aggregate x5 per head: acc5[dst][h][64] = w_self*x5[dst] + sum w_e*x5[src]
__global__ __launch_bounds__(256)
void csr_agg5(const float* __restrict__ x5, int n)
{
    int warpid = (blockIdx.x*256 + threadIdx.x) >> 5;
    if (warpid >= n) return;
    int lane = threadIdx.x & 31;
    int dst = warpid;
    int c0 = lane*2;

    float sd_l = (lane < HEADS) ? g_sd[dst*HEADS + lane] : 0.f;
    float wv = (lane < HEADS) ? __expf(lrelu(g_ss[dst*HEADS + lane] + sd_l)) : 0.f;
    float dsum = wv;

    float2 xv = *(const float2*)(x5 + (size_t)dst*D1 + c0);
    float acc[16];
#pragma unroll
    for (int h = 0; h < HEADS; h++) {
        float w = __shfl_sync(0xffffffffu, wv, h);
        acc[2*h]   = w * xv.x;
        acc[2*h+1] = w * xv.y;
    }

    int beg = g_row[dst], end = g_row[dst+1];
    for (int j0 = beg; j0 < end; j0 += 32) {
        int myj = j0 + lane;
        int mysrc = (myj < end) ? g_col[myj] : 0;
        int m = min(32, end - j0);
        for (int t = 0; t < m; t++) {
            int s = __shfl_sync(0xffffffffu, mysrc, t);
            float we = (lane < HEADS) ? __expf(lrelu(g_ss[s*HEADS + lane] + sd_l)) : 0.f;
            float2 v = *(const float2*)(x5 + (size_t)s*D1 + c0);
#pragma unroll
            for (int h = 0; h < HEADS; h++) {
                float w = __shfl_sync(0xffffffffu, we, h);
                acc[2*h]   = fmaf(w, v.x, acc[2*h]);
                acc[2*h+1] = fmaf(w, v.y, acc[2*h+1]);
            }
            if (lane < HEADS) dsum += we;
        }
    }
    float* ap = g_acc5 + (size_t)dst*512;
#pragma unroll
    for (int h = 0; h < HEADS; h++)
        *(float2*)(ap + h*D1 + c0) = make_float2(acc[2*h], acc[2*h+1]);
    if (lane < HEADS) g_dn[dst*HEADS + lane] = dsum;
}

// y_h = (acc5[node][h]/dn) @ W5_slice(h)  -> g_h5[node][h][40]
__global__ __launch_bounds__(128)
void gemm5b(const float* __restrict__ W5, int n)
{
    int head = blockIdx.y;
    __shared__ float Ws[D1*NCLS];
    for (int i = threadIdx.x; i < D1*NCLS; i += 128) {
        int k = i / NCLS, c = i % NCLS;
        Ws[i] = W5[k*D5 + head*NCLS + c];
    }
    __syncthreads();

    int node = blockIdx.x*128 + threadIdx.x;
    if (node >= n) return;

    float rdn = 1.f / g_dn[node*HEADS + head];
    float acc[NCLS];
#pragma unroll
    for (int c = 0; c < NCLS; c++) acc[c] = 0.f;

    const float4* ap = (const float4*)(g_acc5 + (size_t)node*512 + head*D1);
#pragma unroll
    for (int k4 = 0; k4 < D1/4; k4++) {
        float4 v = ap[k4];
        float xs[4] = {v.x, v.y, v.z, v.w};
#pragma unroll
        for (int j = 0; j < 4; j++) {
            float x = xs[j] * rdn;
            const float* wr = &Ws[(k4*4 + j)*NCLS];
#pragma unroll
            for (int c = 0; c < NCLS; c++) acc[c] = fmaf(x, wr[c], acc[c]);
        }
    }
    float* hp = g_h5 + (size_t)node*D5 + head*NCLS;
#pragma unroll
    for (int i = 0; i < NCLS/4; i++)
        ((float4*)hp)[i] = make_float4(acc[4*i], acc[4*i+1], acc[4*i+2], acc[4*i+3]);
}

// mean over heads + b5 + log_softmax
__global__ __launch_bounds__(128)
void finalize2(const float* __restrict__ b5, float* __restrict__ out, int n)
{
    int node = blockIdx.x*128 + threadIdx.x;
    if (node >= n) return;
    float v[NCLS];
#pragma unroll
    for (int c = 0; c < NCLS; c++) v[c] = 0.f;
#pragma unroll
    for (int h = 0; h < HEADS; h++) {
        const float* hp = g_h5 + (size_t)node*D5 + h*NCLS;
#pragma unroll
        for (int c = 0; c < NCLS; c++) v[c] += hp[c];
    }
    float m = -1e30f;
#pragma unroll
    for (int c = 0; c < NCLS; c++) {
        v[c] = v[c] * 0.125f + b5[c];
        m = fmaxf(m, v[c]);
    }
    float sum = 0.f;
#pragma unroll
    for (int c = 0; c < NCLS; c++) sum += expf(v[c] - m);
    float lse = m + logf(sum);
    float* op = out + (size_t)node*NCLS;
#pragma unroll
    for (int c = 0; c < NCLS; c++) op[c] = v[c] - lse;
}

// ======================= launch =======================
extern "C" void kernel_launch(void* const* d_in, const int* in_sizes, int n_in,
                              void* d_out, int out_size)
{
    const float* x  = (const float*)d_in[0];
    const int*   ei = (const int*)d_in[1];
    int E = in_sizes[1] / 2;
    int n = in_sizes[0] / 128;
    const int* srcp = ei;
    const int* dstp = ei + E;

    const float *W[5], *as_[5], *ad_[5], *bs[5];
    for (int l = 0; l < 5; l++) {
        W[l]   = (const float*)d_in[2 + 4*l];
        as_[l] = (const float*)d_in[3 + 4*l];
        ad_[l] = (const float*)d_in[4 + 4*l];
        bs[l]  = (const float*)d_in[5 + 4*l];
    }

    float *bufA, *bufB;
    cudaGetSymbolAddress((void**)&bufA, g_bufA);
    cudaGetSymbolAddress((void**)&bufB, g_bufB);

    int gn256  = (n + 255) / 256;
    int gn128  = (n + 127) / 128;
    int ge256  = (E + 255) / 256;
    int gwarp  = (n*32 + 255) / 256;

    // CSR build (graph shared by all 5 layers)
    zero_cnt<<<gn256, 256>>>(n);
    count_kernel<<<ge256, 256>>>(dstp, E);
    scan_kernel<<<1, 1024>>>(n);
    scatter_kernel<<<ge256, 256>>>(srcp, dstp, E);
    w5a_kernel<<<(HEADS*D1 + 127)/128, 128>>>(W[4], as_[4], ad_[4]);

    // Layer 1
    gemm_node<128, false><<<gn256, 256>>>(x, W[0], as_[0], ad_[0], nullptr, bufA, n);
    csr_agg<<<gwarp, 256>>>(bufA, bufB, n);

    // Layers 2-4
    for (int l = 1; l <= 3; l++) {
        gemm_node<64, true><<<gn256, 256>>>(bufB, W[l], as_[l], ad_[l], bs[l-1], bufA, n);
        csr_agg<<<gwarp, 256>>>(bufA, bufB, n);
    }

    // Layer 5: aggregate pre-GEMM activations, then per-head GEMM
    x5_kernel<<<gn256, 256>>>(bufB, bs[3], bufA, n);
    csr_agg5<<<gwarp, 256>>>(bufA, n);
    gemm5b<<<dim3(gn128, HEADS), 128>>>(W[4], n);
    finalize2<<<gn128, 128>>>(bs[4], (float*)d_out, n);
}